// round 15
// baseline (speedup 1.0000x reference)
#include <cuda_runtime.h>

// out[row] = sum_l in[row*1024 + l] / (l+1),  rows = 131072, L = 1024.
//
// FINAL — converged kernel (4 runs of this exact source: 81.9 / 84.5 / 82.7
// / 84.5 us; DRAM 81-84%; distribution ~83 ± 1.5 us):
//  - One resident wave: 760 blocks (152 SMs x 5), balanced contiguous
//    per-warp row ranges. Search bounds: dynamic queues (R6/R7) -8..12%;
//    4-row batching (R9) -6%; low occupancy (R1) -10%; launch-shape
//    variants ncu-identical.
//  - Weights 1/(l+1) in 4KB smem, once per block (regs=48, occ ~60%).
//  - Per row: 8 front-batched float4 __ldcs loads (MLP=8) — load-bearing
//    issue pattern; do not perturb.
//  - Rows in pairs, 6-shuffle joint reduction; lanes 0/16 write.
// Binder: device HBM bandwidth (~6.5 TB/s sustained = 81-84% of 8 TB/s
// spec). SM-side resources 5-15x over-provisioned (issue ~11%). At the
// streaming roofline; remaining headroom < run-to-run noise.

static constexpr int L       = 1024;
static constexpr int ROWS    = 4 * 8 * 4096;   // 131072
static constexpr int THREADS = 256;            // 8 warps
static constexpr int GRID    = 152 * 5;        // one full wave at 5 blocks/SM

__device__ __forceinline__ float row_partial(const float* __restrict__ in,
                                             const float4* __restrict__ w4,
                                             int lane, int row) {
    const float4* p = reinterpret_cast<const float4*>(in + (size_t)row * L) + lane;

    // Front-batch 8 loads (MLP=8 per warp), read-once streaming.
    float4 v[8];
    #pragma unroll
    for (int k = 0; k < 8; k++) {
        v[k] = __ldcs(p + k * 32);   // warp stride = 32 float4 = 128 floats
    }

    float s0 = 0.0f, s1 = 0.0f;
    #pragma unroll
    for (int k = 0; k < 8; k++) {
        float4 w = w4[lane + 32 * k];
        s0 = fmaf(v[k].x, w.x, s0);
        s1 = fmaf(v[k].y, w.y, s1);
        s0 = fmaf(v[k].z, w.z, s0);
        s1 = fmaf(v[k].w, w.w, s1);
    }
    return s0 + s1;
}

__global__ __launch_bounds__(THREADS, 5)
void fractal_dim_kernel(const float* __restrict__ in, float* __restrict__ out) {
    __shared__ float4 w4[L / 4];   // w4[i] = {1/(4i+1), ..., 1/(4i+4)}

    const int t = threadIdx.x;
    {
        int base = t * 4;
        float4 w;
        w.x = 1.0f / (float)(base + 1);
        w.y = 1.0f / (float)(base + 2);
        w.z = 1.0f / (float)(base + 3);
        w.w = 1.0f / (float)(base + 4);
        w4[t] = w;
    }
    __syncthreads();

    const int lane = t & 31;
    const int wid  = t >> 5;

    // Balanced contiguous split: block range, then warp range within it.
    const int bstart = (int)((long long)blockIdx.x       * ROWS / GRID);
    const int bend   = (int)((long long)(blockIdx.x + 1) * ROWS / GRID);
    const int n      = bend - bstart;
    const int wstart = bstart + (int)((long long)wid       * n / 8);
    const int wend   = bstart + (int)((long long)(wid + 1) * n / 8);

    int row = wstart;

    // ── Paired rows: 6-shuffle joint reduction ──
    for (; row + 1 < wend; row += 2) {
        float sA = row_partial(in, w4, lane, row);
        float sB = row_partial(in, w4, lane, row + 1);

        // Cross-half exchange, then select A into lanes 0-15, B into 16-31.
        float xa = sA + __shfl_xor_sync(0xffffffffu, sA, 16);
        float xb = sB + __shfl_xor_sync(0xffffffffu, sB, 16);
        float z  = (lane < 16) ? xa : xb;

        #pragma unroll
        for (int off = 8; off > 0; off >>= 1) {
            z += __shfl_xor_sync(0xffffffffu, z, off);
        }

        if (lane == 0)  out[row]     = z;   // full sum of row A
        if (lane == 16) out[row + 1] = z;   // full sum of row B
    }

    // ── Possible odd final row ──
    if (row < wend) {
        float s = row_partial(in, w4, lane, row);
        #pragma unroll
        for (int off = 16; off > 0; off >>= 1) {
            s += __shfl_xor_sync(0xffffffffu, s, off);
        }
        if (lane == 0) out[row] = s;
    }
}

extern "C" void kernel_launch(void* const* d_in, const int* in_sizes, int n_in,
                              void* d_out, int out_size) {
    const float* in  = (const float*)d_in[0];
    float*       out = (float*)d_out;
    fractal_dim_kernel<<<GRID, THREADS>>>(in, out);
}

// round 16
// speedup vs baseline: 1.0264x; 1.0264x over previous
#include <cuda_runtime.h>

// out[row] = sum_l in[row*1024 + l] / (l+1),  rows = 131072, L = 1024.
//
// FINAL — converged kernel. Five runs of this exact source:
//   bench 81.9 / 84.5 / 82.7 / 84.5 / 84.7 us (mean ~83.5, sigma ~1.2)
//   ncu   81.7 / 82.9 / 83.0 / 84.3 / 83.4 us, DRAM 81-84%
// Structure:
//  - One resident wave: 760 blocks (152 SMs x 5), balanced contiguous
//    per-warp row ranges (static).
//  - Weights 1/(l+1) in 4KB smem, once per block (regs=48, occ ~60%).
//  - Per row: 8 front-batched float4 __ldcs loads (MLP=8) — load-bearing
//    issue pattern.
//  - Rows in pairs, 6-shuffle joint reduction; lanes 0/16 write.
// Measured search bounds (all >> noise): dynamic queues -8..12% (R6/R7),
// 4-row batching -6% (R9), occ 34% -10% (R1); launch-shape & occupancy
// variations ncu-identical (R2/R5). Binder: device HBM bandwidth
// (~6.5 TB/s sustained = 81-84% of 8 TB/s spec); SM-side 5-15x
// over-provisioned (issue ~11%). Remaining headroom < run-to-run noise.

static constexpr int L       = 1024;
static constexpr int ROWS    = 4 * 8 * 4096;   // 131072
static constexpr int THREADS = 256;            // 8 warps
static constexpr int GRID    = 152 * 5;        // one full wave at 5 blocks/SM

__device__ __forceinline__ float row_partial(const float* __restrict__ in,
                                             const float4* __restrict__ w4,
                                             int lane, int row) {
    const float4* p = reinterpret_cast<const float4*>(in + (size_t)row * L) + lane;

    // Front-batch 8 loads (MLP=8 per warp), read-once streaming.
    float4 v[8];
    #pragma unroll
    for (int k = 0; k < 8; k++) {
        v[k] = __ldcs(p + k * 32);   // warp stride = 32 float4 = 128 floats
    }

    float s0 = 0.0f, s1 = 0.0f;
    #pragma unroll
    for (int k = 0; k < 8; k++) {
        float4 w = w4[lane + 32 * k];
        s0 = fmaf(v[k].x, w.x, s0);
        s1 = fmaf(v[k].y, w.y, s1);
        s0 = fmaf(v[k].z, w.z, s0);
        s1 = fmaf(v[k].w, w.w, s1);
    }
    return s0 + s1;
}

__global__ __launch_bounds__(THREADS, 5)
void fractal_dim_kernel(const float* __restrict__ in, float* __restrict__ out) {
    __shared__ float4 w4[L / 4];   // w4[i] = {1/(4i+1), ..., 1/(4i+4)}

    const int t = threadIdx.x;
    {
        int base = t * 4;
        float4 w;
        w.x = 1.0f / (float)(base + 1);
        w.y = 1.0f / (float)(base + 2);
        w.z = 1.0f / (float)(base + 3);
        w.w = 1.0f / (float)(base + 4);
        w4[t] = w;
    }
    __syncthreads();

    const int lane = t & 31;
    const int wid  = t >> 5;

    // Balanced contiguous split: block range, then warp range within it.
    const int bstart = (int)((long long)blockIdx.x       * ROWS / GRID);
    const int bend   = (int)((long long)(blockIdx.x + 1) * ROWS / GRID);
    const int n      = bend - bstart;
    const int wstart = bstart + (int)((long long)wid       * n / 8);
    const int wend   = bstart + (int)((long long)(wid + 1) * n / 8);

    int row = wstart;

    // ── Paired rows: 6-shuffle joint reduction ──
    for (; row + 1 < wend; row += 2) {
        float sA = row_partial(in, w4, lane, row);
        float sB = row_partial(in, w4, lane, row + 1);

        // Cross-half exchange, then select A into lanes 0-15, B into 16-31.
        float xa = sA + __shfl_xor_sync(0xffffffffu, sA, 16);
        float xb = sB + __shfl_xor_sync(0xffffffffu, sB, 16);
        float z  = (lane < 16) ? xa : xb;

        #pragma unroll
        for (int off = 8; off > 0; off >>= 1) {
            z += __shfl_xor_sync(0xffffffffu, z, off);
        }

        if (lane == 0)  out[row]     = z;   // full sum of row A
        if (lane == 16) out[row + 1] = z;   // full sum of row B
    }

    // ── Possible odd final row ──
    if (row < wend) {
        float s = row_partial(in, w4, lane, row);
        #pragma unroll
        for (int off = 16; off > 0; off >>= 1) {
            s += __shfl_xor_sync(0xffffffffu, s, off);
        }
        if (lane == 0) out[row] = s;
    }
}

extern "C" void kernel_launch(void* const* d_in, const int* in_sizes, int n_in,
                              void* d_out, int out_size) {
    const float* in  = (const float*)d_in[0];
    float*       out = (float*)d_out;
    fractal_dim_kernel<<<GRID, THREADS>>>(in, out);
}